// round 4
// baseline (speedup 1.0000x reference)
#include <cuda_runtime.h>
#include <cstdint>

typedef unsigned long long u64;

#define VOCAB   10000
#define EMB     256
#define UNITS   128
#define NG      512        // 4 * UNITS, gate order i,f,c,o
#define BATCH   256
#define SEQ     1024

#define NTHREADS 256
#define NBLOCKS  128       // 64 clusters of 2 CTAs; 4 batch rows per cluster

// Precomputed gate table: G[v][c] = sum_e emb[v][e]*Wk[e][c] + b[c]   (20.5 MB)
__device__ float g_G[VOCAB * NG];

// ---------------- helpers ----------------
__device__ __forceinline__ u64 fma2(u64 a, u64 b, u64 c) {
    u64 d;
    asm("fma.rn.f32x2 %0, %1, %2, %3;" : "=l"(d) : "l"(a), "l"(b), "l"(c));
    return d;
}
__device__ __forceinline__ u64 pk2(float x, float y) {
    u64 r;
    asm("mov.b64 %0, {%1, %2};" : "=l"(r) : "f"(x), "f"(y));
    return r;
}
__device__ __forceinline__ float2 upk2(u64 v) {
    float2 r;
    asm("mov.b64 {%0, %1}, %2;" : "=f"(r.x), "=f"(r.y) : "l"(v));
    return r;
}
__device__ __forceinline__ float sigmoidf(float x) {
    return __fdividef(1.0f, 1.0f + __expf(-x));
}
__device__ __forceinline__ uint32_t smem_u32(const void* p) {
    uint32_t a;
    asm("{ .reg .u64 t; cvta.to.shared.u64 t, %1; cvt.u32.u64 %0, t; }" : "=r"(a) : "l"(p));
    return a;
}
__device__ __forceinline__ uint32_t ctarank() {
    uint32_t r; asm("mov.u32 %0, %%cluster_ctarank;" : "=r"(r)); return r;
}
__device__ __forceinline__ uint32_t mapa_u32(uint32_t addr, uint32_t rank) {
    uint32_t r;
    asm("mapa.shared::cluster.u32 %0, %1, %2;" : "=r"(r) : "r"(addr), "r"(rank));
    return r;
}
__device__ __forceinline__ void mbar_init(uint32_t mbar, uint32_t cnt) {
    asm volatile("mbarrier.init.shared.b64 [%0], %1;" :: "r"(mbar), "r"(cnt) : "memory");
}
__device__ __forceinline__ void mbar_arrive_remote(uint32_t remote_mbar) {
    asm volatile("mbarrier.arrive.release.cluster.shared::cluster.b64 _, [%0];"
                 :: "r"(remote_mbar) : "memory");
}
__device__ __forceinline__ void mbar_wait(uint32_t mbar, uint32_t phase) {
    uint32_t done;
    do {
        asm volatile(
            "{\n\t.reg .pred p;\n\t"
            "mbarrier.try_wait.parity.acquire.cluster.shared::cta.b64 p, [%1], %2, 0x989680;\n\t"
            "selp.b32 %0, 1, 0, p;\n\t}"
            : "=r"(done) : "r"(mbar), "r"(phase) : "memory");
    } while (!done);
}
__device__ __forceinline__ void st_remote_f32(uint32_t addr, float v) {
    asm volatile("st.shared::cluster.f32 [%0], %1;" :: "r"(addr), "f"(v) : "memory");
}

// ---------------- Kernel 1: G = emb @ Wk + b ----------------
#define VB 16
__global__ void __launch_bounds__(512)
gbuild_kernel(const float* __restrict__ emb, const float* __restrict__ Wk,
              const float* __restrict__ b)
{
    __shared__ float es[VB][EMB];
    const int c  = threadIdx.x;
    const int v0 = blockIdx.x * VB;

    for (int i = c; i < VB * EMB; i += 512)
        es[i / EMB][i % EMB] = emb[v0 * EMB + i];
    __syncthreads();

    float acc[VB];
#pragma unroll
    for (int v = 0; v < VB; v++) acc[v] = 0.0f;

    for (int e = 0; e < EMB; e += 4) {
        const float w0 = Wk[(e + 0) * NG + c];
        const float w1 = Wk[(e + 1) * NG + c];
        const float w2 = Wk[(e + 2) * NG + c];
        const float w3 = Wk[(e + 3) * NG + c];
#pragma unroll
        for (int v = 0; v < VB; v++) {
            float4 ev = *(const float4*)&es[v][e];
            acc[v] += ev.x * w0 + ev.y * w1 + ev.z * w2 + ev.w * w3;
        }
    }
    const float bc = b[c];
#pragma unroll
    for (int v = 0; v < VB; v++)
        g_G[(v0 + v) * NG + c] = acc[v] + bc;
}

// ---------------- Kernel 2: clustered persistent LSTM ----------------
// 2-CTA cluster handles 4 batch rows. CTA rank r owns units [64r,64r+64)
// i.e. gate-columns {64r + ul + 128g}. All Wr columns it needs live in
// REGISTERS (128 regs/thread): thread j = (kh<<7)|jc, kh = k-half,
// jc -> 2 columns (gates gA, gA+2 of unit 64r+(jc&63)), 64 k-rows each.
// Per step: FMA partials -> zp smem -> local gates for own units ->
// h_new stored locally + DSMEM to peer. Two mbarriers/CTA:
//   REMOTE_OK: peer finished reading its h_s -> I may write peer h_s
//   H_READY  : peer's units of my h_s have arrived
//
// Dynamic smem:
//   [0]  mbar REMOTE_OK (8B), [8] mbar H_READY (8B), pad to 32
//   zp  [2][256][4] float   8192 B   @32
//   h_s [4][128]    float   2048 B   @8224
//   xs  [4][1024]   int    16384 B   @10272
#define ZP_OFF   32
#define H_OFF    (ZP_OFF + 2 * 256 * 4 * 4)
#define XS_OFF   (H_OFF + 4 * UNITS * 4)
#define SMEM_TOTAL (XS_OFF + 4 * SEQ * 4)

__global__ void __launch_bounds__(NTHREADS, 1) __cluster_dims__(2, 1, 1)
lstm_kernel(const int* __restrict__ x, const float* __restrict__ Wr,
            const float* __restrict__ Wd, const float* __restrict__ bd,
            float* __restrict__ out)
{
    extern __shared__ char smem[];
    float (*zp)[256][4] = (float (*)[256][4])(smem + ZP_OFF);
    float* h_s = (float*)(smem + H_OFF);
    int*   xs  = (int*)  (smem + XS_OFF);

    const uint32_t smem_base = smem_u32(smem);
    const uint32_t mb_rok = smem_base;          // REMOTE_OK
    const uint32_t mb_hrd = smem_base + 8;      // H_READY

    const int j    = threadIdx.x;
    const uint32_t rank = ctarank();
    const uint32_t peer = rank ^ 1u;
    const int clus = blockIdx.x >> 1;

    // FMA-role indices
    const int kh  = j >> 7;             // k half: [64kh, 64kh+64)
    const int jc  = j & 127;
    const int gA  = jc >> 6;            // gates gA and gA+2
    const int ulf = jc & 63;
    const int cA  = 64 * rank + ulf + 128 * gA;
    const int cB  = 64 * rank + ulf + 128 * (gA + 2);
    const int lcA = (gA << 6) | ulf;          // local col 0..127
    const int lcB = ((gA + 2) << 6) | ulf;    // local col 128..255

    // gate-role indices: one (unit,row) per thread
    const int u_l  = j & 63;
    const int grow = j >> 6;            // 0..3
    const int u_g  = 64 * rank + u_l;   // global unit

    // peer addresses
    const uint32_t mb_rok_peer = mapa_u32(mb_rok, peer);
    const uint32_t mb_hrd_peer = mapa_u32(mb_hrd, peer);
    const uint32_t h_rem = mapa_u32(smem_base + H_OFF + (grow * UNITS + u_g) * 4, peer);

    // ---- setup ----
    if (j == 0) { mbar_init(mb_rok, 1); mbar_init(mb_hrd, 1); }
    for (int i = j; i < 4 * SEQ; i += NTHREADS) {
        int row = i >> 10, tt = i & (SEQ - 1);
        xs[i] = x[(clus * 4 + row) * SEQ + tt];
    }
    for (int i = j; i < 4 * UNITS; i += NTHREADS) h_s[i] = 0.0f;

    // register weights: 2 cols x 32 f32x2 pairs
    u64 w0[32], w1[32];
#pragma unroll
    for (int kk = 0; kk < 32; kk++) {
        const int k = 64 * kh + 2 * kk;
        w0[kk] = pk2(Wr[k * NG + cA], Wr[(k + 1) * NG + cA]);
        w1[kk] = pk2(Wr[k * NG + cB], Wr[(k + 1) * NG + cB]);
    }
    __syncthreads();
    asm volatile("barrier.cluster.arrive.aligned;" ::: "memory");
    asm volatile("barrier.cluster.wait.aligned;"   ::: "memory");

    float c_state = 0.0f;
    const float* hb = h_s + 64 * kh;    // this thread's k-half base

    for (int t = 0; t < SEQ; t++) {
        const uint32_t par = (uint32_t)(t & 1);

        // prefetch gate-table gathers for my (unit,row)
        const int tok = xs[grow * SEQ + t];
        const float* gr = g_G + (size_t)tok * NG + u_g;
        const float xg0 = gr[0];
        const float xg1 = gr[128];
        const float xg2 = gr[256];
        const float xg3 = gr[384];

        // ---- FMA phase: partial z over my k-half, 2 cols x 4 rows ----
        u64 a0[4], a1[4];
#pragma unroll
        for (int r = 0; r < 4; r++) { a0[r] = 0ull; a1[r] = 0ull; }
#pragma unroll
        for (int kk = 0; kk < 32; kk += 2) {
#pragma unroll
            for (int r = 0; r < 4; r++) {
                ulonglong2 hv = *(const ulonglong2*)(hb + r * UNITS + 2 * kk);
                a0[r] = fma2(w0[kk],     hv.x, a0[r]);
                a0[r] = fma2(w0[kk + 1], hv.y, a0[r]);
                a1[r] = fma2(w1[kk],     hv.x, a1[r]);
                a1[r] = fma2(w1[kk + 1], hv.y, a1[r]);
            }
        }
        {
            float4 sA, sB;
            float2 p;
            p = upk2(a0[0]); sA.x = p.x + p.y;
            p = upk2(a0[1]); sA.y = p.x + p.y;
            p = upk2(a0[2]); sA.z = p.x + p.y;
            p = upk2(a0[3]); sA.w = p.x + p.y;
            p = upk2(a1[0]); sB.x = p.x + p.y;
            p = upk2(a1[1]); sB.y = p.x + p.y;
            p = upk2(a1[2]); sB.z = p.x + p.y;
            p = upk2(a1[3]); sB.w = p.x + p.y;
            *(float4*)&zp[kh][lcA][0] = sA;
            *(float4*)&zp[kh][lcB][0] = sB;
        }
        __syncthreads();                       // zp ready; done reading h_s(t)
        if (j == 0) mbar_arrive_remote(mb_rok_peer);   // peer may write my h_s

        // ---- gates for my (unit,row) ----
        const float zi = zp[0][(0 << 6) | u_l][grow] + zp[1][(0 << 6) | u_l][grow] + xg0;
        const float zf = zp[0][(1 << 6) | u_l][grow] + zp[1][(1 << 6) | u_l][grow] + xg1;
        const float zc = zp[0][(2 << 6) | u_l][grow] + zp[1][(2 << 6) | u_l][grow] + xg2;
        const float zo = zp[0][(3 << 6) | u_l][grow] + zp[1][(3 << 6) | u_l][grow] + xg3;
        const float ig = sigmoidf(zi);
        const float fg = sigmoidf(zf);
        const float gg = fmaxf(zc, 0.0f);
        const float og = sigmoidf(zo);
        c_state = fg * c_state + ig * gg;
        const float hn = og * fmaxf(c_state, 0.0f);

        mbar_wait(mb_rok, par);                // peer done reading peer h_s
        h_s[grow * UNITS + u_g] = hn;          // local
        st_remote_f32(h_rem, hn);              // peer
        __syncthreads();                       // all h stores issued/ordered
        if (j == 0) mbar_arrive_remote(mb_hrd_peer);
        mbar_wait(mb_hrd, par);                // peer's units arrived in my h_s
    }

    // ---- dense head (rank 0 writes the cluster's 4 rows) ----
    if (rank == 0 && j < 8) {
        const int rr = j >> 1, oc = j & 1;
        float acc = bd[oc];
        for (int uu = 0; uu < UNITS; uu++)
            acc += h_s[rr * UNITS + uu] * Wd[uu * 2 + oc];
        out[(clus * 4 + rr) * 2 + oc] = acc;
    }
}

// ---------------- launch ----------------
extern "C" void kernel_launch(void* const* d_in, const int* in_sizes, int n_in,
                              void* d_out, int out_size)
{
    const int*   x   = 0;
    const float *emb = 0, *Wk = 0, *Wr = 0, *bb = 0, *Wd = 0, *bd = 0;
    for (int i = 0; i < n_in; i++) {
        switch (in_sizes[i]) {                       // all sizes are distinct
            case BATCH * SEQ: x   = (const int*)  d_in[i]; break;  // 262144
            case VOCAB * EMB: emb = (const float*)d_in[i]; break;  // 2560000
            case EMB * NG:    Wk  = (const float*)d_in[i]; break;  // 131072
            case UNITS * NG:  Wr  = (const float*)d_in[i]; break;  // 65536
            case NG:          bb  = (const float*)d_in[i]; break;  // 512
            case UNITS * 2:   Wd  = (const float*)d_in[i]; break;  // 256
            case 2:           bd  = (const float*)d_in[i]; break;
        }
    }

    gbuild_kernel<<<VOCAB / VB, 512>>>(emb, Wk, bb);
    lstm_kernel<<<NBLOCKS, NTHREADS, SMEM_TOTAL>>>(x, Wr, Wd, bd, (float*)d_out);
}

// round 5
// speedup vs baseline: 1.3293x; 1.3293x over previous
#include <cuda_runtime.h>
#include <cstdint>

typedef unsigned long long u64;

#define VOCAB   10000
#define EMB     256
#define UNITS   128
#define NG      512        // 4 * UNITS, gate order i,f,c,o
#define BATCH   256
#define SEQ     1024

#define NTHREADS 256
#define NBLOCKS  128       // 2 batch rows per block, one wave of 128 SMs

// Precomputed gate table: G[v][c] = sum_e emb[v][e]*Wk[e][c] + b[c]   (20.5 MB)
__device__ float g_G[VOCAB * NG];

// ---------------- f32x2 helpers (Blackwell packed fp32) ----------------
__device__ __forceinline__ u64 fma2(u64 a, u64 b, u64 c) {
    u64 d;
    asm("fma.rn.f32x2 %0, %1, %2, %3;" : "=l"(d) : "l"(a), "l"(b), "l"(c));
    return d;
}
__device__ __forceinline__ u64 pk2(float x, float y) {
    u64 r;
    asm("mov.b64 %0, {%1, %2};" : "=l"(r) : "f"(x), "f"(y));
    return r;
}
__device__ __forceinline__ float2 upk2(u64 v) {
    float2 r;
    asm("mov.b64 {%0, %1}, %2;" : "=f"(r.x), "=f"(r.y) : "l"(v));
    return r;
}
__device__ __forceinline__ float sigmoidf(float x) {
    return __fdividef(1.0f, 1.0f + __expf(-x));
}

// ---------------- Kernel 1: G = emb @ Wk + b  (2.6 GFLOP) ----------------
#define VB 16
__global__ void __launch_bounds__(512)
gbuild_kernel(const float* __restrict__ emb, const float* __restrict__ Wk,
              const float* __restrict__ b)
{
    __shared__ float es[VB][EMB];           // 16 KB tile of embedding rows
    const int c  = threadIdx.x;             // column 0..511
    const int v0 = blockIdx.x * VB;

    for (int i = c; i < VB * EMB; i += 512)
        es[i / EMB][i % EMB] = emb[v0 * EMB + i];
    __syncthreads();

    float acc[VB];
#pragma unroll
    for (int v = 0; v < VB; v++) acc[v] = 0.0f;

    for (int e = 0; e < EMB; e += 4) {
        const float w0 = Wk[(e + 0) * NG + c];
        const float w1 = Wk[(e + 1) * NG + c];
        const float w2 = Wk[(e + 2) * NG + c];
        const float w3 = Wk[(e + 3) * NG + c];
#pragma unroll
        for (int v = 0; v < VB; v++) {
            float4 ev = *(const float4*)&es[v][e];
            acc[v] += ev.x * w0 + ev.y * w1 + ev.z * w2 + ev.w * w3;
        }
    }
    const float bc = b[c];
#pragma unroll
    for (int v = 0; v < VB; v++)
        g_G[(v0 + v) * NG + c] = acc[v] + bc;
}

// ---------------- Kernel 2: persistent LSTM recurrence ----------------
// 128 CTAs x 256 threads, 2 batch rows per CTA, ALL of Wr in registers:
// thread j owns gate-columns {j, j+256}; per column 128 k-rows packed as
// 64 f32x2 pairs -> w0[64] + w1[64] = 128 u64 registers. Zero per-step
// weight memory traffic. Per step:
//   FMA phase (reads h broadcast from smem) -> z staging -> bar ->
//   gate phase (one (unit,row) per thread) -> h write -> bar.
__global__ void __launch_bounds__(NTHREADS, 1)
lstm_kernel(const int* __restrict__ x, const float* __restrict__ Wr,
            const float* __restrict__ Wd, const float* __restrict__ bd,
            float* __restrict__ out)
{
    __shared__ float h_s[2 * UNITS];        // hidden state, rows 0/1
    __shared__ float z_s[2 * NG];           // staged z, rows 0/1
    __shared__ int   xs[2 * SEQ];           // tokens for this CTA's rows

    const int j   = threadIdx.x;            // 0..255
    const int blk = blockIdx.x;             // 0..127

    // ---- one-time setup ----
    for (int i = j; i < 2 * SEQ; i += NTHREADS) {
        int row = i >> 10, tt = i & (SEQ - 1);
        xs[i] = x[(blk * 2 + row) * SEQ + tt];
    }
    // full-k register weights for cols j and j+256: pair kk = k-rows {2kk,2kk+1}
    u64 w0[64], w1[64];
#pragma unroll
    for (int kk = 0; kk < 64; kk++) {
        w0[kk] = pk2(Wr[(2 * kk) * NG + j],       Wr[(2 * kk + 1) * NG + j]);
        w1[kk] = pk2(Wr[(2 * kk) * NG + j + 256], Wr[(2 * kk + 1) * NG + j + 256]);
    }
    for (int i = j; i < 2 * UNITS; i += NTHREADS) h_s[i] = 0.0f;
    __syncthreads();

    const int u   = j & (UNITS - 1);        // gate-phase unit
    const int row = j >> 7;                 // gate-phase batch row
    float c_state = 0.0f;

    const float* h0p = h_s;                 // row 0 hidden state
    const float* h1p = h_s + UNITS;         // row 1

    for (int t = 0; t < SEQ; t++) {
        // prefetch this step's gate-table gathers (consumed after FMA phase)
        const int tok = xs[row * SEQ + t];
        const float* gr = g_G + (size_t)tok * NG + u;
        const float xg0 = gr[0];
        const float xg1 = gr[128];
        const float xg2 = gr[256];
        const float xg3 = gr[384];

        // ---- FMA phase: z = h @ Wr for my two columns, both rows ----
        // pairs kk,kk+1 cover k-rows {2kk..2kk+3} == h[2kk..2kk+3]
        u64 acc00 = 0ull, acc01 = 0ull, acc10 = 0ull, acc11 = 0ull;
#pragma unroll
        for (int kk = 0; kk < 64; kk += 2) {
            ulonglong2 hv0 = *(const ulonglong2*)(h0p + 2 * kk);
            ulonglong2 hv1 = *(const ulonglong2*)(h1p + 2 * kk);
            acc00 = fma2(w0[kk],     hv0.x, acc00);
            acc00 = fma2(w0[kk + 1], hv0.y, acc00);
            acc01 = fma2(w0[kk],     hv1.x, acc01);
            acc01 = fma2(w0[kk + 1], hv1.y, acc01);
            acc10 = fma2(w1[kk],     hv0.x, acc10);
            acc10 = fma2(w1[kk + 1], hv0.y, acc10);
            acc11 = fma2(w1[kk],     hv1.x, acc11);
            acc11 = fma2(w1[kk + 1], hv1.y, acc11);
        }
        {
            float2 a00 = upk2(acc00), a01 = upk2(acc01);
            float2 a10 = upk2(acc10), a11 = upk2(acc11);
            z_s[0 * NG + j]       = a00.x + a00.y;
            z_s[1 * NG + j]       = a01.x + a01.y;
            z_s[0 * NG + j + 256] = a10.x + a10.y;
            z_s[1 * NG + j + 256] = a11.x + a11.y;
        }
        __syncthreads();                    // z ready; FMA reads of h done

        // ---- gate phase: my (unit,row) ----
        const float zi = z_s[row * NG + u]       + xg0;
        const float zf = z_s[row * NG + u + 128] + xg1;
        const float zc = z_s[row * NG + u + 256] + xg2;
        const float zo = z_s[row * NG + u + 384] + xg3;
        const float ig = sigmoidf(zi);
        const float fg = sigmoidf(zf);
        const float gg = fmaxf(zc, 0.0f);   // activation = relu
        const float og = sigmoidf(zo);
        c_state = fg * c_state + ig * gg;
        const float hn = og * fmaxf(c_state, 0.0f);
        h_s[row * UNITS + u] = hn;
        __syncthreads();                    // h(t+1) visible to all
    }

    // ---- dense head: out[row] = h @ Wd + bd ----
    if (j < 4) {
        const int rr = j >> 1, oc = j & 1;
        float acc = bd[oc];
        for (int uu = 0; uu < UNITS; uu++)
            acc += h_s[rr * UNITS + uu] * Wd[uu * 2 + oc];
        out[(blk * 2 + rr) * 2 + oc] = acc;
    }
}

// ---------------- launch ----------------
extern "C" void kernel_launch(void* const* d_in, const int* in_sizes, int n_in,
                              void* d_out, int out_size)
{
    const int*   x   = 0;
    const float *emb = 0, *Wk = 0, *Wr = 0, *bb = 0, *Wd = 0, *bd = 0;
    for (int i = 0; i < n_in; i++) {
        switch (in_sizes[i]) {                       // all sizes are distinct
            case BATCH * SEQ: x   = (const int*)  d_in[i]; break;  // 262144
            case VOCAB * EMB: emb = (const float*)d_in[i]; break;  // 2560000
            case EMB * NG:    Wk  = (const float*)d_in[i]; break;  // 131072
            case UNITS * NG:  Wr  = (const float*)d_in[i]; break;  // 65536
            case NG:          bb  = (const float*)d_in[i]; break;  // 512
            case UNITS * 2:   Wd  = (const float*)d_in[i]; break;  // 256
            case 2:           bd  = (const float*)d_in[i]; break;
        }
    }

    gbuild_kernel<<<VOCAB / VB, 512>>>(emb, Wk, bb);
    lstm_kernel<<<NBLOCKS, NTHREADS>>>(x, Wr, Wd, bd, (float*)d_out);
}

// round 6
// speedup vs baseline: 1.6197x; 1.2184x over previous
#include <cuda_runtime.h>
#include <cstdint>

typedef unsigned long long u64;

#define VOCAB   10000
#define EMB     256
#define UNITS   128
#define NG      512        // 4 * UNITS, gate order i,f,c,o
#define BATCH   256
#define SEQ     1024

// Wr k-split: rows [0,KR) in registers, [KR,128) in shared memory
#define KR      80
#define KRP     40         // KR/2 f32x2 pairs
#define KS      48
#define KSP     24         // KS/2

#define NTHREADS 256
#define NBLOCKS  128       // 2 batch rows per block, one wave

// Precomputed gate table: G[v][c] = sum_e emb[v][e]*Wk[e][c] + b[c]  (20.5 MB)
__device__ float g_G[VOCAB * NG];

// ---------------- f32x2 helpers ----------------
__device__ __forceinline__ u64 fma2(u64 a, u64 b, u64 c) {
    u64 d;
    asm("fma.rn.f32x2 %0, %1, %2, %3;" : "=l"(d) : "l"(a), "l"(b), "l"(c));
    return d;
}
__device__ __forceinline__ u64 pk2(float x, float y) {
    u64 r;
    asm("mov.b64 %0, {%1, %2};" : "=l"(r) : "f"(x), "f"(y));
    return r;
}
__device__ __forceinline__ float2 upk2(u64 v) {
    float2 r;
    asm("mov.b64 {%0, %1}, %2;" : "=f"(r.x), "=f"(r.y) : "l"(v));
    return r;
}
__device__ __forceinline__ float sigmoidf(float x) {
    return __fdividef(1.0f, 1.0f + __expf(-x));
}

// ---------------- Kernel 1: G = emb @ Wk + b ----------------
#define VB 16
__global__ void __launch_bounds__(512)
gbuild_kernel(const float* __restrict__ emb, const float* __restrict__ Wk,
              const float* __restrict__ b)
{
    __shared__ float es[VB][EMB];
    const int c  = threadIdx.x;
    const int v0 = blockIdx.x * VB;

    for (int i = c; i < VB * EMB; i += 512)
        es[i / EMB][i % EMB] = emb[v0 * EMB + i];
    __syncthreads();

    float acc[VB];
#pragma unroll
    for (int v = 0; v < VB; v++) acc[v] = 0.0f;

    for (int e = 0; e < EMB; e += 4) {
        const float w0 = Wk[(e + 0) * NG + c];
        const float w1 = Wk[(e + 1) * NG + c];
        const float w2 = Wk[(e + 2) * NG + c];
        const float w3 = Wk[(e + 3) * NG + c];
#pragma unroll
        for (int v = 0; v < VB; v++) {
            float4 ev = *(const float4*)&es[v][e];
            acc[v] += ev.x * w0 + ev.y * w1 + ev.z * w2 + ev.w * w3;
        }
    }
    const float bc = b[c];
#pragma unroll
    for (int v = 0; v < VB; v++)
        g_G[(v0 + v) * NG + c] = acc[v] + bc;
}

// ---------------- Kernel 2: persistent LSTM recurrence ----------------
// 128 CTAs x 256 threads, 2 batch rows per CTA.
// Thread j: u = j>>1, p = j&1. Owns gate-cols cA = 128p+u (gate p) and
// cB = 128(p+2)+u (gate p+2), for BOTH rows. After the FMA phase the lane
// pair (2u, 2u+1) swaps two z values via shfl.xor(1) so the thread holds
// all 4 gate pre-activations of unit u for row p; it then runs the
// nonlinearity + cell update locally (c_state in a register).
//
// h is stored interleaved by k-pairs and double-buffered:
//   hbuf[buf][kk] = float4 { r0[2kk], r0[2kk+1], r1[2kk], r1[2kk+1] }
// so ONE LDS.128 feeds both rows' fma2 operands, and a single
// __syncthreads per step is sufficient (write buf (t+1)&1, read t&1).
//
// Smem weights (k in [KR,128)) are gate-blocked with stride 129 u64 so
// lane pairs (2u,2u+1) hit disjoint banks: ws(kk,g,u) = kk*516 + g*129 + u.
#define WS_U64   (KSP * 516)             // 12384 u64
#define WS_BYTES (WS_U64 * 8)            // 99072 B
#define HB_OFF   WS_BYTES                // 2 bufs x 128 u64 = 2048 B
#define XS_OFF   (HB_OFF + 2048)
#define SMEM_TOTAL (XS_OFF + 2 * SEQ * 4)

__global__ void __launch_bounds__(NTHREADS, 1)
lstm_kernel(const int* __restrict__ x, const float* __restrict__ Wr,
            const float* __restrict__ Wd, const float* __restrict__ bd,
            float* __restrict__ out)
{
    extern __shared__ char smem[];
    u64*   Ws   = (u64*)smem;
    u64*   hbuf = (u64*)(smem + HB_OFF);  // [2][128] u64 (= [2][64] float4)
    int*   xs   = (int*)(smem + XS_OFF);

    const int j   = threadIdx.x;
    const int blk = blockIdx.x;
    const int u   = j >> 1;
    const int p   = j & 1;
    const int cA  = 128 * p + u;          // gate p
    const int cB  = 128 * (p + 2) + u;    // gate p+2

    // ---- one-time setup ----
    for (int i = j; i < 2 * SEQ; i += NTHREADS) {
        int row = i >> 10, tt = i & (SEQ - 1);
        xs[i] = x[(blk * 2 + row) * SEQ + tt];
    }
    // register weights: k in [0,KR), pair kk = k-rows {2kk, 2kk+1}
    u64 w0[KRP], w1[KRP];
#pragma unroll
    for (int kk = 0; kk < KRP; kk++) {
        w0[kk] = pk2(Wr[(2 * kk) * NG + cA], Wr[(2 * kk + 1) * NG + cA]);
        w1[kk] = pk2(Wr[(2 * kk) * NG + cB], Wr[(2 * kk + 1) * NG + cB]);
    }
    // smem weights: k in [KR,128), gate-blocked stride-129 layout
    for (int i = j; i < KSP * NG; i += NTHREADS) {
        int kk = i >> 9, c = i & (NG - 1);
        int g = c >> 7, uu = c & 127;
        int k = KR + 2 * kk;
        Ws[kk * 516 + g * 129 + uu] = pk2(Wr[k * NG + c], Wr[(k + 1) * NG + c]);
    }
    // zero both h buffers
    for (int i = j; i < 256; i += NTHREADS) hbuf[i] = 0ull;
    __syncthreads();

    float c_state = 0.0f;

    for (int t = 0; t < SEQ; t++) {
        const u64* hc = hbuf + ((t & 1) << 7);       // current h, 128 u64

        // prefetch gate-table gathers for (unit u, row p)
        const int tok = xs[p * SEQ + t];
        const float* gr = g_G + (size_t)tok * NG + u;
        const float xg0 = gr[0];
        const float xg1 = gr[128];
        const float xg2 = gr[256];
        const float xg3 = gr[384];

        // ---- FMA phase: z for cols cA,cB over both rows ----
        u64 aA0 = 0ull, aA1 = 0ull, aB0 = 0ull, aB1 = 0ull;
#pragma unroll
        for (int kk = 0; kk < KRP; kk++) {
            ulonglong2 hv = *(const ulonglong2*)(hc + 2 * kk);  // .x row0, .y row1
            aA0 = fma2(w0[kk], hv.x, aA0);
            aA1 = fma2(w0[kk], hv.y, aA1);
            aB0 = fma2(w1[kk], hv.x, aB0);
            aB1 = fma2(w1[kk], hv.y, aB1);
        }
#pragma unroll
        for (int kk = 0; kk < KSP; kk++) {
            ulonglong2 hv = *(const ulonglong2*)(hc + 2 * (KRP + kk));
            u64 wsA = Ws[kk * 516 + p * 129 + u];
            u64 wsB = Ws[kk * 516 + (p + 2) * 129 + u];
            aA0 = fma2(wsA, hv.x, aA0);
            aA1 = fma2(wsA, hv.y, aA1);
            aB0 = fma2(wsB, hv.x, aB0);
            aB1 = fma2(wsB, hv.y, aB1);
        }
        float2 s;
        s = upk2(aA0); const float zA0 = s.x + s.y;   // gate p,   row 0
        s = upk2(aA1); const float zA1 = s.x + s.y;   // gate p,   row 1
        s = upk2(aB0); const float zB0 = s.x + s.y;   // gate p+2, row 0
        s = upk2(aB1); const float zB1 = s.x + s.y;   // gate p+2, row 1

        // ---- lane-pair exchange: collect all 4 gates for row p ----
        const float r1 = __shfl_xor_sync(0xffffffffu, p ? zA0 : zA1, 1);
        const float r2 = __shfl_xor_sync(0xffffffffu, p ? zB0 : zB1, 1);
        // even (p=0, row0): zi=zA0 zf=r1 zc=zB0 zo=r2
        // odd  (p=1, row1): zi=r1 zf=zA1 zc=r2 zo=zB1
        const float zi = (p ? r1  : zA0) + xg0;
        const float zf = (p ? zA1 : r1)  + xg1;
        const float zc = (p ? r2  : zB0) + xg2;
        const float zo = (p ? zB1 : r2)  + xg3;

        const float ig = sigmoidf(zi);
        const float fg = sigmoidf(zf);
        const float gg = fmaxf(zc, 0.0f);     // activation = relu
        const float og = sigmoidf(zo);
        c_state = fg * c_state + ig * gg;
        const float hn = og * fmaxf(c_state, 0.0f);

        // write h(t+1) into the other buffer, interleaved layout:
        // word index = (u>>1)*4 + 2p + (u&1)
        float* hnx = (float*)(hbuf + (((t + 1) & 1) << 7));
        hnx[(u >> 1) * 4 + 2 * p + (u & 1)] = hn;
        __syncthreads();
    }

    // ---- dense head: final h lives in buffer 0 (after even SEQ steps) ----
    if (j < 4) {
        const int rr = j >> 1, oc = j & 1;
        const float* hb = (const float*)hbuf;      // buffer 0
        float acc = bd[oc];
        for (int uu = 0; uu < UNITS; uu++)
            acc += hb[(uu >> 1) * 4 + 2 * rr + (uu & 1)] * Wd[uu * 2 + oc];
        out[(blk * 2 + rr) * 2 + oc] = acc;
    }
}

// ---------------- launch ----------------
extern "C" void kernel_launch(void* const* d_in, const int* in_sizes, int n_in,
                              void* d_out, int out_size)
{
    const int*   x   = 0;
    const float *emb = 0, *Wk = 0, *Wr = 0, *bb = 0, *Wd = 0, *bd = 0;
    for (int i = 0; i < n_in; i++) {
        switch (in_sizes[i]) {                       // all sizes are distinct
            case BATCH * SEQ: x   = (const int*)  d_in[i]; break;  // 262144
            case VOCAB * EMB: emb = (const float*)d_in[i]; break;  // 2560000
            case EMB * NG:    Wk  = (const float*)d_in[i]; break;  // 131072
            case UNITS * NG:  Wr  = (const float*)d_in[i]; break;  // 65536
            case NG:          bb  = (const float*)d_in[i]; break;  // 512
            case UNITS * 2:   Wd  = (const float*)d_in[i]; break;  // 256
            case 2:           bd  = (const float*)d_in[i]; break;
        }
    }

    gbuild_kernel<<<VOCAB / VB, 512>>>(emb, Wk, bb);

    cudaFuncSetAttribute(lstm_kernel,
                         cudaFuncAttributeMaxDynamicSharedMemorySize, SMEM_TOTAL);
    lstm_kernel<<<NBLOCKS, NTHREADS, SMEM_TOTAL>>>(x, Wr, Wd, bd, (float*)d_out);
}

// round 7
// speedup vs baseline: 1.8480x; 1.1410x over previous
#include <cuda_runtime.h>
#include <cstdint>

typedef unsigned long long u64;

#define VOCAB   10000
#define EMB     256
#define UNITS   128
#define NG      512        // 4 * UNITS, gate order i,f,c,o
#define BATCH   256
#define SEQ     1024

// Wr k-split: rows [0,KR) in registers, [KR,128) in shared memory
#define KR      80
#define KRP     40         // KR/2 f32x2 pairs
#define KS      48
#define KSP     24         // KS/2

#define NTHREADS 256
#define NBLOCKS  128       // 2 batch rows per block, one wave

// Precomputed gate table: G[v][c] = sum_e emb[v][e]*Wk[e][c] + b[c]  (20.5 MB)
__device__ float g_G[VOCAB * NG];

// ---------------- f32x2 helpers ----------------
__device__ __forceinline__ u64 fma2(u64 a, u64 b, u64 c) {
    u64 d;
    asm("fma.rn.f32x2 %0, %1, %2, %3;" : "=l"(d) : "l"(a), "l"(b), "l"(c));
    return d;
}
__device__ __forceinline__ u64 pk2(float x, float y) {
    u64 r;
    asm("mov.b64 %0, {%1, %2};" : "=l"(r) : "f"(x), "f"(y));
    return r;
}
__device__ __forceinline__ float2 upk2(u64 v) {
    float2 r;
    asm("mov.b64 {%0, %1}, %2;" : "=f"(r.x), "=f"(r.y) : "l"(v));
    return r;
}
__device__ __forceinline__ float sigmoidf(float x) {
    return __fdividef(1.0f, 1.0f + __expf(-x));
}

// ---------------- Kernel 1: G = emb @ Wk + b ----------------
#define VB 16
__global__ void __launch_bounds__(512)
gbuild_kernel(const float* __restrict__ emb, const float* __restrict__ Wk,
              const float* __restrict__ b)
{
    __shared__ float es[VB][EMB];
    const int c  = threadIdx.x;
    const int v0 = blockIdx.x * VB;

    for (int i = c; i < VB * EMB; i += 512)
        es[i / EMB][i % EMB] = emb[v0 * EMB + i];
    __syncthreads();

    float acc[VB];
#pragma unroll
    for (int v = 0; v < VB; v++) acc[v] = 0.0f;

    for (int e = 0; e < EMB; e += 4) {
        const float w0 = Wk[(e + 0) * NG + c];
        const float w1 = Wk[(e + 1) * NG + c];
        const float w2 = Wk[(e + 2) * NG + c];
        const float w3 = Wk[(e + 3) * NG + c];
#pragma unroll
        for (int v = 0; v < VB; v++) {
            float4 ev = *(const float4*)&es[v][e];
            acc[v] += ev.x * w0 + ev.y * w1 + ev.z * w2 + ev.w * w3;
        }
    }
    const float bc = b[c];
#pragma unroll
    for (int v = 0; v < VB; v++)
        g_G[(v0 + v) * NG + c] = acc[v] + bc;
}

// ---------------- Kernel 2: persistent LSTM recurrence ----------------
// 128 CTAs x 256 threads, 2 batch rows per CTA.
// Thread j: u = j>>1, p = j&1. Owns gate-cols cA = 128p+u (gate p) and
// cB = 128(p+2)+u (gate p+2), for BOTH rows; lane pair (2u,2u+1) swaps
// two z values via shfl.xor(1) so each thread gets all 4 gates of unit u
// for row p (c_state in a register). One __syncthreads per step.
//
// h interleaved by k-pairs, double-buffered:
//   hbuf[buf][kk] = float4 { r0[2kk], r0[2kk+1], r1[2kk], r1[2kk+1] }
// -> ONE broadcast LDS.128 feeds both rows' fma2 operands.
//
// Smem weights: W2[kk][j] = ulonglong2 { wA(kk), wB(kk) } for thread j,
// contiguous 16B per lane -> conflict-free LDS.128, one load per kk.
#define WS_BYTES (KSP * NTHREADS * 16)   // 98304 B
#define HB_OFF   WS_BYTES                // 2 bufs x 128 u64 = 2048 B
#define XS_OFF   (HB_OFF + 2048)
#define SMEM_TOTAL (XS_OFF + 2 * SEQ * 4)

__global__ void __launch_bounds__(NTHREADS, 1)
lstm_kernel(const int* __restrict__ x, const float* __restrict__ Wr,
            const float* __restrict__ Wd, const float* __restrict__ bd,
            float* __restrict__ out)
{
    extern __shared__ char smem[];
    ulonglong2* W2  = (ulonglong2*)smem;            // [KSP][256]
    u64*       hbuf = (u64*)(smem + HB_OFF);        // [2][128] u64
    int*       xs   = (int*)(smem + XS_OFF);

    const int j   = threadIdx.x;
    const int blk = blockIdx.x;
    const int u   = j >> 1;
    const int p   = j & 1;
    const int cA  = 128 * p + u;          // gate p
    const int cB  = 128 * (p + 2) + u;    // gate p+2

    // ---- one-time setup ----
    for (int i = j; i < 2 * SEQ; i += NTHREADS) {
        int row = i >> 10, tt = i & (SEQ - 1);
        xs[i] = x[(blk * 2 + row) * SEQ + tt];
    }
    // register weights: k in [0,KR), pair kk = k-rows {2kk, 2kk+1}
    u64 w0[KRP], w1[KRP];
#pragma unroll
    for (int kk = 0; kk < KRP; kk++) {
        w0[kk] = pk2(Wr[(2 * kk) * NG + cA], Wr[(2 * kk + 1) * NG + cA]);
        w1[kk] = pk2(Wr[(2 * kk) * NG + cB], Wr[(2 * kk + 1) * NG + cB]);
    }
    // smem weights: k in [KR,128), per-thread contiguous 16B
    for (int kk = 0; kk < KSP; kk++) {
        const int k = KR + 2 * kk;
        ulonglong2 wv;
        wv.x = pk2(Wr[k * NG + cA], Wr[(k + 1) * NG + cA]);
        wv.y = pk2(Wr[k * NG + cB], Wr[(k + 1) * NG + cB]);
        W2[kk * NTHREADS + j] = wv;
    }
    // zero both h buffers
    for (int i = j; i < 256; i += NTHREADS) hbuf[i] = 0ull;
    __syncthreads();

    float c_state = 0.0f;

    for (int t = 0; t < SEQ; t++) {
        const u64* hc = hbuf + ((t & 1) << 7);       // current h, 128 u64

        // prefetch gate-table gathers for (unit u, row p)
        const int tok = xs[p * SEQ + t];
        const float* gr = g_G + (size_t)tok * NG + u;
        const float xg0 = gr[0];
        const float xg1 = gr[128];
        const float xg2 = gr[256];
        const float xg3 = gr[384];

        // ---- FMA phase: z for cols cA,cB over both rows ----
        u64 aA0 = 0ull, aA1 = 0ull, aB0 = 0ull, aB1 = 0ull;
#pragma unroll
        for (int kk = 0; kk < KRP; kk++) {
            ulonglong2 hv = *(const ulonglong2*)(hc + 2 * kk);  // .x row0, .y row1
            aA0 = fma2(w0[kk], hv.x, aA0);
            aA1 = fma2(w0[kk], hv.y, aA1);
            aB0 = fma2(w1[kk], hv.x, aB0);
            aB1 = fma2(w1[kk], hv.y, aB1);
        }
#pragma unroll
        for (int kk = 0; kk < KSP; kk++) {
            ulonglong2 hv = *(const ulonglong2*)(hc + 2 * (KRP + kk));
            ulonglong2 wv = W2[kk * NTHREADS + j];
            aA0 = fma2(wv.x, hv.x, aA0);
            aA1 = fma2(wv.x, hv.y, aA1);
            aB0 = fma2(wv.y, hv.x, aB0);
            aB1 = fma2(wv.y, hv.y, aB1);
        }
        float2 s;
        s = upk2(aA0); const float zA0 = s.x + s.y;   // gate p,   row 0
        s = upk2(aA1); const float zA1 = s.x + s.y;   // gate p,   row 1
        s = upk2(aB0); const float zB0 = s.x + s.y;   // gate p+2, row 0
        s = upk2(aB1); const float zB1 = s.x + s.y;   // gate p+2, row 1

        // ---- lane-pair exchange: collect all 4 gates for row p ----
        const float r1 = __shfl_xor_sync(0xffffffffu, p ? zA0 : zA1, 1);
        const float r2 = __shfl_xor_sync(0xffffffffu, p ? zB0 : zB1, 1);
        // even (p=0, row0): zi=zA0 zf=r1 zc=zB0 zo=r2
        // odd  (p=1, row1): zi=r1 zf=zA1 zc=r2 zo=zB1
        const float zi = (p ? r1  : zA0) + xg0;
        const float zf = (p ? zA1 : r1)  + xg1;
        const float zc = (p ? r2  : zB0) + xg2;
        const float zo = (p ? zB1 : r2)  + xg3;

        const float ig = sigmoidf(zi);
        const float fg = sigmoidf(zf);
        const float gg = fmaxf(zc, 0.0f);     // activation = relu
        const float og = sigmoidf(zo);
        c_state = fg * c_state + ig * gg;
        const float hn = og * fmaxf(c_state, 0.0f);

        // write h(t+1) into the other buffer, interleaved layout:
        // float word index = (u>>1)*4 + 2p + (u&1)
        float* hnx = (float*)(hbuf + (((t + 1) & 1) << 7));
        hnx[(u >> 1) * 4 + 2 * p + (u & 1)] = hn;
        __syncthreads();
    }

    // ---- dense head: final h lives in buffer 0 (SEQ is even) ----
    if (j < 4) {
        const int rr = j >> 1, oc = j & 1;
        const float* hb = (const float*)hbuf;      // buffer 0
        float acc = bd[oc];
        for (int uu = 0; uu < UNITS; uu++)
            acc += hb[(uu >> 1) * 4 + 2 * rr + (uu & 1)] * Wd[uu * 2 + oc];
        out[(blk * 2 + rr) * 2 + oc] = acc;
    }
}

// ---------------- launch ----------------
extern "C" void kernel_launch(void* const* d_in, const int* in_sizes, int n_in,
                              void* d_out, int out_size)
{
    const int*   x   = 0;
    const float *emb = 0, *Wk = 0, *Wr = 0, *bb = 0, *Wd = 0, *bd = 0;
    for (int i = 0; i < n_in; i++) {
        switch (in_sizes[i]) {                       // all sizes are distinct
            case BATCH * SEQ: x   = (const int*)  d_in[i]; break;  // 262144
            case VOCAB * EMB: emb = (const float*)d_in[i]; break;  // 2560000
            case EMB * NG:    Wk  = (const float*)d_in[i]; break;  // 131072
            case UNITS * NG:  Wr  = (const float*)d_in[i]; break;  // 65536
            case NG:          bb  = (const float*)d_in[i]; break;  // 512
            case UNITS * 2:   Wd  = (const float*)d_in[i]; break;  // 256
            case 2:           bd  = (const float*)d_in[i]; break;
        }
    }

    gbuild_kernel<<<VOCAB / VB, 512>>>(emb, Wk, bb);

    cudaFuncSetAttribute(lstm_kernel,
                         cudaFuncAttributeMaxDynamicSharedMemorySize, SMEM_TOTAL);
    lstm_kernel<<<NBLOCKS, NTHREADS, SMEM_TOTAL>>>(x, Wr, Wd, bd, (float*)d_out);
}